// round 1
// baseline (speedup 1.0000x reference)
#include <cuda_runtime.h>
#include <cuda_bf16.h>

// Problem dims (fixed by the reference)
#define T_   2048   // tokens (B*S)
#define H_   2048   // hidden
#define E_   16     // routed experts
#define K_   4      // top-k
#define I_   1408   // routed intermediate
#define IS_  2816   // shared intermediate
#define CAP_ 1024   // per-expert capacity

// ---------------- scratch (device globals; no allocations allowed) ----------
__device__ float g_Gr[E_ * CAP_ * I_];      // routed gate activations  [E,CAP,I]
__device__ float g_Mr[E_ * CAP_ * I_];      // routed mid = silu(g)*up  [E,CAP,I]
__device__ float g_Eout[E_ * CAP_ * H_];    // routed expert outputs    [E,CAP,H]
__device__ float g_Gs[T_ * IS_];            // shared gate activations  [T,IS]
__device__ float g_Ms[T_ * IS_];            // shared mid               [T,IS]
__device__ int   g_buf[E_ * CAP_];          // token id per (expert,slot)
__device__ int   g_pos[T_ * K_];            // slot of (token,k) in its expert; -1 if dropped
__device__ int   g_cnt[E_];                 // filled slots per expert (capped at CAP)
__device__ int   g_ti[T_ * K_];             // top-k expert ids per token
__device__ float g_tw[T_ * K_];             // normalized top-k weights per token

// ---------------- gate: logits -> softmax-topk -> normalized weights --------
__global__ void gate_topk_kernel(const float* __restrict__ x,
                                 const float* __restrict__ gw)
{
    int t = blockIdx.x;
    const float* xr = x + (size_t)t * H_;
    float acc[E_];
#pragma unroll
    for (int e = 0; e < E_; e++) acc[e] = 0.f;

    for (int h = threadIdx.x; h < H_; h += 256) {
        float xv = xr[h];
#pragma unroll
        for (int e = 0; e < E_; e++) acc[e] += xv * gw[e * H_ + h];
    }
    // warp reduce
#pragma unroll
    for (int e = 0; e < E_; e++) {
#pragma unroll
        for (int o = 16; o > 0; o >>= 1)
            acc[e] += __shfl_down_sync(0xffffffffu, acc[e], o);
    }
    __shared__ float sw[8][E_];
    int warp = threadIdx.x >> 5, lane = threadIdx.x & 31;
    if (lane == 0) {
#pragma unroll
        for (int e = 0; e < E_; e++) sw[warp][e] = acc[e];
    }
    __syncthreads();
    if (threadIdx.x == 0) {
        float lg[E_];
#pragma unroll
        for (int e = 0; e < E_; e++) {
            float s = 0.f;
            for (int w = 0; w < 8; w++) s += sw[w][e];
            lg[e] = s;
        }
        float m = lg[0];
#pragma unroll
        for (int e = 1; e < E_; e++) m = fmaxf(m, lg[e]);

        bool used[E_];
#pragma unroll
        for (int e = 0; e < E_; e++) used[e] = false;

        float wsel[K_]; int isel[K_]; float s = 0.f;
#pragma unroll
        for (int k = 0; k < K_; k++) {
            int best = 0; float bv = -1e30f;
            for (int e = 0; e < E_; e++) {
                if (!used[e] && lg[e] > bv) { bv = lg[e]; best = e; }
            }
            used[best] = true;
            isel[k] = best;
            wsel[k] = expf(lg[best] - m);   // softmax Z cancels in renorm
            s += wsel[k];
        }
        float inv = 1.f / s;
#pragma unroll
        for (int k = 0; k < K_; k++) {
            g_ti[t * K_ + k] = isel[k];
            g_tw[t * K_ + k] = wsel[k] * inv;
        }
    }
}

// ---------------- dispatch: stable rank within each expert -------------------
// Matches jnp.argsort(flat_i) stable semantics: slot order = ascending flat idx.
__global__ void dispatch_kernel()
{
    int e   = blockIdx.x;       // one block per expert
    int tid = threadIdx.x;      // 256 threads
    const int PER = (T_ * K_) / 256;   // 32 contiguous slots/thread
    int base = tid * PER;

    int c = 0;
    for (int j = 0; j < PER; j++)
        if (g_ti[base + j] == e) c++;

    __shared__ int ps[256];
    ps[tid] = c;
    __syncthreads();
    // inclusive Hillis-Steele scan
    for (int off = 1; off < 256; off <<= 1) {
        int v = 0;
        if (tid >= off) v = ps[tid - off];
        __syncthreads();
        ps[tid] += v;
        __syncthreads();
    }
    int total = ps[255];
    int rank  = ps[tid] - c;    // exclusive prefix

    for (int j = 0; j < PER; j++) {
        int idx = base + j;
        if (g_ti[idx] == e) {
            if (rank < CAP_) {
                g_buf[e * CAP_ + rank] = idx >> 2;   // token id
                g_pos[idx] = rank;
            } else {
                g_pos[idx] = -1;                     // dropped (capacity overflow)
            }
            rank++;
        }
    }
    if (tid == 0) g_cnt[e] = total < CAP_ ? total : CAP_;
}

// ---------------- SGEMM 128x128x16, 256 thr, 8x8/thread ----------------------
// GATHER: A rows indirected through g_buf (per-expert token gather)
// EPI==0: C = acc        EPI==1: C = silu(G) * acc  (G same layout as C)
template <bool GATHER, int EPI>
__global__ __launch_bounds__(256, 2)
void sgemm_kernel(const float* __restrict__ A, const float* __restrict__ B,
                  float* __restrict__ C, const float* __restrict__ G,
                  const int* __restrict__ rows, const int* __restrict__ cnt,
                  int Mfull, int N, int Kd,
                  long long sA, long long sB, long long sC)
{
    const int z = blockIdx.z;
    int Mz = Mfull;
    if (cnt) { int c = cnt[z]; Mz = c < Mfull ? c : Mfull; }
    if ((int)blockIdx.y * 128 >= Mz) return;

    const float* Bb = B + (size_t)z * sB;
    float*       Cb = C + (size_t)z * sC;
    const float* Gb = (EPI == 1) ? (G + (size_t)z * sC) : nullptr;

    __shared__ float As[16][128];
    __shared__ float Bs[16][128];

    const int tid = threadIdx.x;
    const int tx = tid & 15, ty = tid >> 4;

    // A-tile load plan: 2 float4 per thread, element (m, k4*4..k4*4+3)
    const float* aP[2]; int am[2], ak[2]; bool aV[2];
#pragma unroll
    for (int i = 0; i < 2; i++) {
        int id = tid + i * 256;            // 0..511
        int m  = id >> 2, k4 = id & 3;
        am[i] = m; ak[i] = k4 * 4;
        int  mg = blockIdx.y * 128 + m;
        bool v  = mg < Mz;
        aV[i] = v;
        long long row;
        const float* base;
        if (GATHER) { row = v ? (long long)rows[z * CAP_ + mg] : 0; base = A; }
        else        { row = mg; base = A + (size_t)z * sA; }
        aP[i] = base + row * (long long)Kd + k4 * 4;
    }
    // B-tile load plan: 2 float4 per thread, element (k, n4*4..)
    const float* bP[2]; int bk[2], bn[2];
#pragma unroll
    for (int i = 0; i < 2; i++) {
        int id = tid + i * 256;
        int k = id >> 5, n4 = id & 31;
        bk[i] = k; bn[i] = n4 * 4;
        bP[i] = Bb + (size_t)k * N + blockIdx.x * 128 + n4 * 4;
    }

    float acc[8][8];
#pragma unroll
    for (int i = 0; i < 8; i++)
#pragma unroll
        for (int j = 0; j < 8; j++) acc[i][j] = 0.f;

    for (int k0 = 0; k0 < Kd; k0 += 16) {
#pragma unroll
        for (int i = 0; i < 2; i++) {
            float4 v = make_float4(0.f, 0.f, 0.f, 0.f);
            if (aV[i]) v = *(const float4*)(aP[i] + k0);
            As[ak[i] + 0][am[i]] = v.x;
            As[ak[i] + 1][am[i]] = v.y;
            As[ak[i] + 2][am[i]] = v.z;
            As[ak[i] + 3][am[i]] = v.w;
        }
#pragma unroll
        for (int i = 0; i < 2; i++) {
            float4 v = *(const float4*)bP[i];
            bP[i] += (size_t)16 * N;
            *(float4*)&Bs[bk[i]][bn[i]] = v;
        }
        __syncthreads();
#pragma unroll
        for (int kk = 0; kk < 16; kk++) {
            float4 a0 = *(const float4*)&As[kk][ty * 8];
            float4 a1 = *(const float4*)&As[kk][ty * 8 + 4];
            float4 b0 = *(const float4*)&Bs[kk][tx * 8];
            float4 b1 = *(const float4*)&Bs[kk][tx * 8 + 4];
            float a[8] = {a0.x, a0.y, a0.z, a0.w, a1.x, a1.y, a1.z, a1.w};
            float b[8] = {b0.x, b0.y, b0.z, b0.w, b1.x, b1.y, b1.z, b1.w};
#pragma unroll
            for (int i = 0; i < 8; i++)
#pragma unroll
                for (int j = 0; j < 8; j++) acc[i][j] += a[i] * b[j];
        }
        __syncthreads();
    }

    int rb = blockIdx.y * 128 + ty * 8;
    int cb = blockIdx.x * 128 + tx * 8;
#pragma unroll
    for (int i = 0; i < 8; i++) {
        int r = rb + i;
        if (r < Mz) {
            size_t off = (size_t)r * N + cb;
            if (EPI == 0) {
                *(float4*)&Cb[off]     = make_float4(acc[i][0], acc[i][1], acc[i][2], acc[i][3]);
                *(float4*)&Cb[off + 4] = make_float4(acc[i][4], acc[i][5], acc[i][6], acc[i][7]);
            } else {
                float4 g0 = *(const float4*)&Gb[off];
                float4 g1 = *(const float4*)&Gb[off + 4];
                float gg[8] = {g0.x, g0.y, g0.z, g0.w, g1.x, g1.y, g1.z, g1.w};
                float o[8];
#pragma unroll
                for (int j = 0; j < 8; j++) {
                    float s = gg[j] / (1.f + __expf(-gg[j]));   // silu
                    o[j] = s * acc[i][j];
                }
                *(float4*)&Cb[off]     = make_float4(o[0], o[1], o[2], o[3]);
                *(float4*)&Cb[off + 4] = make_float4(o[4], o[5], o[6], o[7]);
            }
        }
    }
}

// ---------------- combine: out[t] = shared[t] + sum_k w * eout[e_k, pos_k] ---
__global__ void combine_kernel(float* __restrict__ out)
{
    int t   = blockIdx.x;
    int tid = threadIdx.x;

    const float* rp[K_]; float w[K_]; bool v[K_];
#pragma unroll
    for (int k = 0; k < K_; k++) {
        int p = g_pos[t * K_ + k];
        int e = g_ti[t * K_ + k];
        w[k]  = g_tw[t * K_ + k];
        v[k]  = (p >= 0);
        int pc = p < 0 ? 0 : p;
        rp[k] = g_Eout + ((size_t)e * CAP_ + pc) * H_;
    }
#pragma unroll
    for (int j = 0; j < 2; j++) {
        int c4 = tid + j * 256;            // float4 index, 512 total
        size_t off = (size_t)t * H_ + c4 * 4;
        float4 a = *(float4*)&out[off];
#pragma unroll
        for (int k = 0; k < K_; k++) {
            if (v[k]) {
                float4 xv = *(const float4*)&rp[k][c4 * 4];
                a.x += w[k] * xv.x; a.y += w[k] * xv.y;
                a.z += w[k] * xv.z; a.w += w[k] * xv.w;
            }
        }
        *(float4*)&out[off] = a;
    }
}

// ---------------- launch ------------------------------------------------------
extern "C" void kernel_launch(void* const* d_in, const int* in_sizes, int n_in,
                              void* d_out, int out_size)
{
    const float* x       = (const float*)d_in[0];   // [1,2048,2048]
    const float* gate_w  = (const float*)d_in[1];   // [16,2048]
    const float* w_gate  = (const float*)d_in[2];   // [16,2048,1408]
    const float* w_up    = (const float*)d_in[3];   // [16,2048,1408]
    const float* w_down  = (const float*)d_in[4];   // [16,1408,2048]
    const float* sw_gate = (const float*)d_in[5];   // [2048,2816]
    const float* sw_up   = (const float*)d_in[6];   // [2048,2816]
    const float* sw_down = (const float*)d_in[7];   // [2816,2048]
    float* out = (float*)d_out;

    float *Gr, *Mr, *Eo, *Gs, *Ms;
    int *buf, *cnt;
    cudaGetSymbolAddress((void**)&Gr,  g_Gr);
    cudaGetSymbolAddress((void**)&Mr,  g_Mr);
    cudaGetSymbolAddress((void**)&Eo,  g_Eout);
    cudaGetSymbolAddress((void**)&Gs,  g_Gs);
    cudaGetSymbolAddress((void**)&Ms,  g_Ms);
    cudaGetSymbolAddress((void**)&buf, g_buf);
    cudaGetSymbolAddress((void**)&cnt, g_cnt);

    // 1) routing
    gate_topk_kernel<<<T_, 256>>>(x, gate_w);
    dispatch_kernel<<<E_, 256>>>();

    // 2) routed experts
    dim3 g1(I_ / 128, CAP_ / 128, E_);
    sgemm_kernel<true, 0><<<g1, 256>>>(x, w_gate, Gr, nullptr, buf, cnt,
                                       CAP_, I_, H_, 0, (long long)H_ * I_, (long long)CAP_ * I_);
    sgemm_kernel<true, 1><<<g1, 256>>>(x, w_up, Mr, Gr, buf, cnt,
                                       CAP_, I_, H_, 0, (long long)H_ * I_, (long long)CAP_ * I_);
    dim3 g2(H_ / 128, CAP_ / 128, E_);
    sgemm_kernel<false, 0><<<g2, 256>>>(Mr, w_down, Eo, nullptr, nullptr, cnt,
                                        CAP_, H_, I_, (long long)CAP_ * I_,
                                        (long long)I_ * H_, (long long)CAP_ * H_);

    // 3) shared expert
    dim3 g3(IS_ / 128, T_ / 128, 1);
    sgemm_kernel<false, 0><<<g3, 256>>>(x, sw_gate, Gs, nullptr, nullptr, nullptr,
                                        T_, IS_, H_, 0, 0, 0);
    sgemm_kernel<false, 1><<<g3, 256>>>(x, sw_up, Ms, Gs, nullptr, nullptr,
                                        T_, IS_, H_, 0, 0, 0);
    dim3 g4(H_ / 128, T_ / 128, 1);
    sgemm_kernel<false, 0><<<g4, 256>>>(Ms, sw_down, out, nullptr, nullptr, nullptr,
                                        T_, H_, IS_, 0, 0, 0);

    // 4) combine routed contributions into out (deterministic gather, no atomics)
    combine_kernel<<<T_, 256>>>(out);
}

// round 8
// speedup vs baseline: 2.0411x; 2.0411x over previous
#include <cuda_runtime.h>
#include <cuda_bf16.h>
#include <cstdint>

// Problem dims (fixed by the reference)
#define T_   2048   // tokens (B*S)
#define H_   2048   // hidden
#define E_   16     // routed experts
#define K_   4      // top-k
#define I_   1408   // routed intermediate
#define IS_  2816   // shared intermediate
#define CAP_ 1024   // per-expert capacity

// ---------------- scratch (device globals; no allocations allowed) ----------
__device__ float g_Gr[E_ * CAP_ * I_];      // routed gate activations  [E,CAP,I]
__device__ float g_Mr[E_ * CAP_ * I_];      // routed mid = silu(g)*up  [E,CAP,I]
__device__ float g_Eout[E_ * CAP_ * H_];    // routed expert outputs    [E,CAP,H]
__device__ float g_Gs[T_ * IS_];            // shared gate activations  [T,IS]
__device__ float g_Ms[T_ * IS_];            // shared mid               [T,IS]
__device__ int   g_buf[E_ * CAP_];          // token id per (expert,slot)
__device__ int   g_pos[T_ * K_];            // slot of (token,k); -1 if dropped
__device__ int   g_cnt[E_];                 // filled slots per expert
__device__ int   g_ti[T_ * K_];             // top-k expert ids
__device__ float g_tw[T_ * K_];             // normalized top-k weights

// ======================= helpers ==============================
__device__ __forceinline__ uint32_t smem_u32(const void* p) {
    uint32_t a;
    asm("{ .reg .u64 t; cvta.to.shared.u64 t, %1; cvt.u32.u64 %0, t; }"
        : "=r"(a) : "l"(p));
    return a;
}
__device__ __forceinline__ void ldsm4(uint32_t* r, uint32_t addr) {
    asm volatile("ldmatrix.sync.aligned.m8n8.x4.shared.b16 {%0,%1,%2,%3}, [%4];"
                 : "=r"(r[0]), "=r"(r[1]), "=r"(r[2]), "=r"(r[3]) : "r"(addr));
}
__device__ __forceinline__ void ldsm4t(uint32_t* r, uint32_t addr) {
    asm volatile("ldmatrix.sync.aligned.m8n8.x4.trans.shared.b16 {%0,%1,%2,%3}, [%4];"
                 : "=r"(r[0]), "=r"(r[1]), "=r"(r[2]), "=r"(r[3]) : "r"(addr));
}
__device__ __forceinline__ void mma16816(float* d, const uint32_t* a, const uint32_t* b) {
    asm volatile("mma.sync.aligned.m16n8k16.row.col.f32.bf16.bf16.f32 "
                 "{%0,%1,%2,%3}, {%4,%5,%6,%7}, {%8,%9}, {%0,%1,%2,%3};"
                 : "+f"(d[0]), "+f"(d[1]), "+f"(d[2]), "+f"(d[3])
                 : "r"(a[0]), "r"(a[1]), "r"(a[2]), "r"(a[3]), "r"(b[0]), "r"(b[1]));
}
__device__ __forceinline__ uint32_t pack_hi(float x, float y) {
    return (uint32_t)__bfloat16_as_ushort(__float2bfloat16_rn(x))
         | ((uint32_t)__bfloat16_as_ushort(__float2bfloat16_rn(y)) << 16);
}
__device__ __forceinline__ uint32_t pack_lo(float x, float y) {
    float rx = x - __bfloat162float(__float2bfloat16_rn(x));
    float ry = y - __bfloat162float(__float2bfloat16_rn(y));
    return (uint32_t)__bfloat16_as_ushort(__float2bfloat16_rn(rx))
         | ((uint32_t)__bfloat16_as_ushort(__float2bfloat16_rn(ry)) << 16);
}

// ---------------- gate: logits -> softmax-topk -> normalized weights --------
__global__ void gate_topk_kernel(const float* __restrict__ x,
                                 const float* __restrict__ gw)
{
    int t = blockIdx.x;
    const float* xr = x + (size_t)t * H_;
    float acc[E_];
#pragma unroll
    for (int e = 0; e < E_; e++) acc[e] = 0.f;

    for (int h = threadIdx.x; h < H_; h += 256) {
        float xv = xr[h];
#pragma unroll
        for (int e = 0; e < E_; e++) acc[e] += xv * gw[e * H_ + h];
    }
#pragma unroll
    for (int e = 0; e < E_; e++) {
#pragma unroll
        for (int o = 16; o > 0; o >>= 1)
            acc[e] += __shfl_down_sync(0xffffffffu, acc[e], o);
    }
    __shared__ float sw[8][E_];
    int warp = threadIdx.x >> 5, lane = threadIdx.x & 31;
    if (lane == 0) {
#pragma unroll
        for (int e = 0; e < E_; e++) sw[warp][e] = acc[e];
    }
    __syncthreads();
    if (threadIdx.x == 0) {
        float lg[E_];
#pragma unroll
        for (int e = 0; e < E_; e++) {
            float s = 0.f;
            for (int w = 0; w < 8; w++) s += sw[w][e];
            lg[e] = s;
        }
        float m = lg[0];
#pragma unroll
        for (int e = 1; e < E_; e++) m = fmaxf(m, lg[e]);

        bool used[E_];
#pragma unroll
        for (int e = 0; e < E_; e++) used[e] = false;

        float wsel[K_]; int isel[K_]; float s = 0.f;
#pragma unroll
        for (int k = 0; k < K_; k++) {
            int best = 0; float bv = -1e30f;
            for (int e = 0; e < E_; e++)
                if (!used[e] && lg[e] > bv) { bv = lg[e]; best = e; }
            used[best] = true;
            isel[k] = best;
            wsel[k] = expf(lg[best] - m);
            s += wsel[k];
        }
        float inv = 1.f / s;
#pragma unroll
        for (int k = 0; k < K_; k++) {
            g_ti[t * K_ + k] = isel[k];
            g_tw[t * K_ + k] = wsel[k] * inv;
        }
    }
}

// ---------------- dispatch: stable rank within each expert -------------------
__global__ void dispatch_kernel()
{
    int e   = blockIdx.x;
    int tid = threadIdx.x;
    const int PER = (T_ * K_) / 256;
    int base = tid * PER;

    int c = 0;
    for (int j = 0; j < PER; j++)
        if (g_ti[base + j] == e) c++;

    __shared__ int ps[256];
    ps[tid] = c;
    __syncthreads();
    for (int off = 1; off < 256; off <<= 1) {
        int v = 0;
        if (tid >= off) v = ps[tid - off];
        __syncthreads();
        ps[tid] += v;
        __syncthreads();
    }
    int total = ps[255];
    int rank  = ps[tid] - c;

    for (int j = 0; j < PER; j++) {
        int idx = base + j;
        if (g_ti[idx] == e) {
            if (rank < CAP_) {
                g_buf[e * CAP_ + rank] = idx >> 2;
                g_pos[idx] = rank;
            } else {
                g_pos[idx] = -1;
            }
            rank++;
        }
    }
    if (tid == 0) g_cnt[e] = total < CAP_ ? total : CAP_;
}

// ============ bf16x3 mma.sync GEMM, tile 128x128, Kc=32, 8 warps =============
// C[M,N] = A[M,K] * B[K,N]  (A fp32 row-major, B fp32 row-major [K,N])
// GATHER: A rows via g_buf.  EPI==1: C = silu(G) * acc.
// SMEM: A hi/lo K-major rows (stride 80B), B hi/lo k-rows of n (stride 272B).
#define A_STR 80
#define B_STR 272
#define SM_AH 0
#define SM_AL (128 * A_STR)            // 10240
#define SM_BH (2 * 128 * A_STR)        // 20480
#define SM_BL (2 * 128 * A_STR + 32 * B_STR)  // 29184
#define SM_SZ (2 * 128 * A_STR + 2 * 32 * B_STR)  // 37888

template <bool GATHER, int EPI>
__global__ __launch_bounds__(256)
void mma_gemm(const float* __restrict__ A, const float* __restrict__ B,
              float* __restrict__ C, const float* __restrict__ G,
              const int* __restrict__ rows, const int* __restrict__ cnt,
              int Mfull, int N, int Kd,
              long long sA, long long sB, long long sC)
{
    __shared__ char smem[SM_SZ];
    const int z = blockIdx.z;
    int Mz = Mfull;
    if (cnt) { int c = cnt[z]; Mz = c < Mfull ? c : Mfull; }
    const int yblk = blockIdx.y * 128;
    if (yblk >= Mz) return;
    const int xblk = blockIdx.x * 128;

    const float* Bb = B + (size_t)z * sB;
    float*       Cb = C + (size_t)z * sC;
    const float* Gb = (EPI == 1) ? (G + (size_t)z * sC) : nullptr;

    const uint32_t sm = smem_u32(smem);
    const int tid = threadIdx.x;
    const int wid = tid >> 5;
    const int lid = tid & 31;

    // ---- per-thread global load plan (4 A-float4, 4 B-float4 per chunk) ----
    const float* aPtr[4]; bool aV[4]; int aRowI[4], aK4[4];
    const float* bPtr[4]; int bK[4], bN4[4];
#pragma unroll
    for (int i = 0; i < 4; i++) {
        int f = tid + 256 * i;                 // 0..1023
        int row = f >> 3, k4 = f & 7;          // A: row, k-quad
        aRowI[i] = row; aK4[i] = k4;
        int mg = yblk + row;
        aV[i] = mg < Mz;
        long long r;
        const float* base;
        if (GATHER) { r = aV[i] ? (long long)rows[z * CAP_ + mg] : 0; base = A; }
        else        { r = mg; base = A + (size_t)z * sA; }
        aPtr[i] = base + r * (long long)Kd + 4 * k4;

        int k = f >> 5, n4 = f & 31;           // B: k-row, n-quad
        bK[i] = k; bN4[i] = n4;
        bPtr[i] = Bb + (size_t)k * N + xblk + 4 * n4;
    }

    const int nch = Kd / 32;
    float4 pa[4], pb[4];
#pragma unroll
    for (int i = 0; i < 4; i++) {
        pa[i] = aV[i] ? *(const float4*)(aPtr[i]) : make_float4(0.f, 0.f, 0.f, 0.f);
        pb[i] = *(const float4*)(bPtr[i]);
    }

    // ---- warp compute geometry ----
    const int wm = wid & 3;        // row group: wm*32..+31
    const int wn = wid >> 2;       // col group: wn*64..+63
    const int l15 = lid & 15, lh = lid >> 4;
    // A ldmatrix addr (per mt tile, per hi/lo): rows wm*32+mt*16+l15, col half lh
    const uint32_t aAdH = sm + SM_AH + (uint32_t)(wm * 32 + l15) * A_STR + lh * 16;
    const uint32_t aAdL = sm + SM_AL + (uint32_t)(wm * 32 + l15) * A_STR + lh * 16;
    // B ldmatrix.trans addr: k row = kk + l15, n = wn*64 + nt*16 + lh*8
    const uint32_t bAdH = sm + SM_BH + (uint32_t)l15 * B_STR + (uint32_t)(wn * 64 + lh * 8) * 2;
    const uint32_t bAdL = sm + SM_BL + (uint32_t)l15 * B_STR + (uint32_t)(wn * 64 + lh * 8) * 2;

    float acc[2][8][4];
#pragma unroll
    for (int mt = 0; mt < 2; mt++)
#pragma unroll
        for (int nt = 0; nt < 8; nt++)
#pragma unroll
            for (int q = 0; q < 4; q++) acc[mt][nt][q] = 0.f;

    for (int ch = 0; ch < nch; ch++) {
        // ---- convert + store to smem ----
#pragma unroll
        for (int i = 0; i < 4; i++) {
            uint32_t off = (uint32_t)aRowI[i] * A_STR + aK4[i] * 8;
            *(uint2*)(smem + SM_AH + off) =
                make_uint2(pack_hi(pa[i].x, pa[i].y), pack_hi(pa[i].z, pa[i].w));
            *(uint2*)(smem + SM_AL + off) =
                make_uint2(pack_lo(pa[i].x, pa[i].y), pack_lo(pa[i].z, pa[i].w));
        }
#pragma unroll
        for (int i = 0; i < 4; i++) {
            uint32_t off = (uint32_t)bK[i] * B_STR + bN4[i] * 8;
            *(uint2*)(smem + SM_BH + off) =
                make_uint2(pack_hi(pb[i].x, pb[i].y), pack_hi(pb[i].z, pb[i].w));
            *(uint2*)(smem + SM_BL + off) =
                make_uint2(pack_lo(pb[i].x, pb[i].y), pack_lo(pb[i].z, pb[i].w));
        }
        __syncthreads();

        // ---- prefetch next chunk's globals (latency hidden behind MMAs) ----
        if (ch + 1 < nch) {
            int ko = (ch + 1) * 32;
#pragma unroll
            for (int i = 0; i < 4; i++) {
                pa[i] = aV[i] ? *(const float4*)(aPtr[i] + ko)
                              : make_float4(0.f, 0.f, 0.f, 0.f);
                pb[i] = *(const float4*)(bPtr[i] + (size_t)ko * N);
            }
        }

        // ---- MMA phase: 2 k16 steps ----
#pragma unroll
        for (int kk = 0; kk < 2; kk++) {
            uint32_t ah[2][4], al[2][4], bh[4][4], bl[4][4];
#pragma unroll
            for (int mt = 0; mt < 2; mt++) {
                ldsm4(ah[mt], aAdH + mt * 16 * A_STR + kk * 32);
                ldsm4(al[mt], aAdL + mt * 16 * A_STR + kk * 32);
            }
#pragma unroll
            for (int nt = 0; nt < 4; nt++) {
                ldsm4t(bh[nt], bAdH + kk * 16 * B_STR + nt * 32);
                ldsm4t(bl[nt], bAdL + kk * 16 * B_STR + nt * 32);
            }
#pragma unroll
            for (int mt = 0; mt < 2; mt++)
#pragma unroll
                for (int nt = 0; nt < 4; nt++) {
                    mma16816(acc[mt][2 * nt],     ah[mt], &bh[nt][0]);
                    mma16816(acc[mt][2 * nt + 1], ah[mt], &bh[nt][2]);
                    mma16816(acc[mt][2 * nt],     ah[mt], &bl[nt][0]);
                    mma16816(acc[mt][2 * nt + 1], ah[mt], &bl[nt][2]);
                    mma16816(acc[mt][2 * nt],     al[mt], &bh[nt][0]);
                    mma16816(acc[mt][2 * nt + 1], al[mt], &bh[nt][2]);
                }
        }
        __syncthreads();
    }

    // ---- epilogue: write accumulators ----
    const int group = lid >> 2, tig = lid & 3;
#pragma unroll
    for (int mt = 0; mt < 2; mt++) {
        int r0 = yblk + wm * 32 + mt * 16 + group;
#pragma unroll
        for (int half = 0; half < 2; half++) {
            int r = r0 + half * 8;
            if (r < Mz) {
                size_t rowoff = (size_t)r * N;
#pragma unroll
                for (int nt = 0; nt < 8; nt++) {
                    int col = xblk + wn * 64 + nt * 8 + 2 * tig;
                    float d0 = acc[mt][nt][2 * half];
                    float d1 = acc[mt][nt][2 * half + 1];
                    if (EPI == 1) {
                        float2 g = *(const float2*)&Gb[rowoff + col];
                        d0 *= g.x / (1.f + __expf(-g.x));
                        d1 *= g.y / (1.f + __expf(-g.y));
                    }
                    *(float2*)&Cb[rowoff + col] = make_float2(d0, d1);
                }
            }
        }
    }
}

// ---------------- combine: out[t] += sum_k w * eout[e_k, pos_k] --------------
__global__ void combine_kernel(float* __restrict__ out)
{
    int t   = blockIdx.x;
    int tid = threadIdx.x;

    const float* rp[K_]; float w[K_]; bool v[K_];
#pragma unroll
    for (int k = 0; k < K_; k++) {
        int p = g_pos[t * K_ + k];
        int e = g_ti[t * K_ + k];
        w[k]  = g_tw[t * K_ + k];
        v[k]  = (p >= 0);
        int pc = p < 0 ? 0 : p;
        rp[k] = g_Eout + ((size_t)e * CAP_ + pc) * H_;
    }
#pragma unroll
    for (int j = 0; j < 2; j++) {
        int c4 = tid + j * 256;
        size_t off = (size_t)t * H_ + c4 * 4;
        float4 a = *(float4*)&out[off];
#pragma unroll
        for (int k = 0; k < K_; k++) {
            if (v[k]) {
                float4 xv = *(const float4*)&rp[k][c4 * 4];
                a.x += w[k] * xv.x; a.y += w[k] * xv.y;
                a.z += w[k] * xv.z; a.w += w[k] * xv.w;
            }
        }
        *(float4*)&out[off] = a;
    }
}

// ---------------- launch ------------------------------------------------------
extern "C" void kernel_launch(void* const* d_in, const int* in_sizes, int n_in,
                              void* d_out, int out_size)
{
    const float* x       = (const float*)d_in[0];
    const float* gate_w  = (const float*)d_in[1];
    const float* w_gate  = (const float*)d_in[2];
    const float* w_up    = (const float*)d_in[3];
    const float* w_down  = (const float*)d_in[4];
    const float* sw_gate = (const float*)d_in[5];
    const float* sw_up   = (const float*)d_in[6];
    const float* sw_down = (const float*)d_in[7];
    float* out = (float*)d_out;

    float *Gr, *Mr, *Eo, *Gs, *Ms;
    int *buf, *cnt;
    cudaGetSymbolAddress((void**)&Gr,  g_Gr);
    cudaGetSymbolAddress((void**)&Mr,  g_Mr);
    cudaGetSymbolAddress((void**)&Eo,  g_Eout);
    cudaGetSymbolAddress((void**)&Gs,  g_Gs);
    cudaGetSymbolAddress((void**)&Ms,  g_Ms);
    cudaGetSymbolAddress((void**)&buf, g_buf);
    cudaGetSymbolAddress((void**)&cnt, g_cnt);

    // 1) routing
    gate_topk_kernel<<<T_, 256>>>(x, gate_w);
    dispatch_kernel<<<E_, 256>>>();

    // 2) routed experts
    dim3 g1(I_ / 128, CAP_ / 128, E_);
    mma_gemm<true, 0><<<g1, 256>>>(x, w_gate, Gr, nullptr, buf, cnt,
        CAP_, I_, H_, 0, (long long)H_ * I_, (long long)CAP_ * I_);
    mma_gemm<true, 1><<<g1, 256>>>(x, w_up, Mr, Gr, buf, cnt,
        CAP_, I_, H_, 0, (long long)H_ * I_, (long long)CAP_ * I_);
    dim3 g2(H_ / 128, CAP_ / 128, E_);
    mma_gemm<false, 0><<<g2, 256>>>(Mr, w_down, Eo, nullptr, nullptr, cnt,
        CAP_, H_, I_, (long long)CAP_ * I_, (long long)I_ * H_, (long long)CAP_ * H_);

    // 3) shared expert
    dim3 g3(IS_ / 128, T_ / 128, 1);
    mma_gemm<false, 0><<<g3, 256>>>(x, sw_gate, Gs, nullptr, nullptr, nullptr,
        T_, IS_, H_, 0, 0, 0);
    mma_gemm<false, 1><<<g3, 256>>>(x, sw_up, Ms, Gs, nullptr, nullptr,
        T_, IS_, H_, 0, 0, 0);
    dim3 g4(H_ / 128, T_ / 128, 1);
    mma_gemm<false, 0><<<g4, 256>>>(Ms, sw_down, out, nullptr, nullptr, nullptr,
        T_, H_, IS_, 0, 0, 0);

    // 4) combine routed contributions (deterministic gather, no atomics)
    combine_kernel<<<T_, 256>>>(out);
}